// round 3
// baseline (speedup 1.0000x reference)
#include <cuda_runtime.h>
#include <math.h>

typedef unsigned long long u64;

// ---- scratch (static device globals; no allocation) ----
__device__ __align__(16) float d_XE[(size_t)64 * 32 * 10 * 1024];  // 80MB  [t][b][p][h]
__device__ __align__(16) float d_h[32 * 1024];                     // [b][h]
__device__ __align__(16) float d_c[32 * 1024];                     // [b][h]
__device__ __align__(16) float d_hWh[32 * 1024];                   // [b][h]  h @ Wh^T
__device__ __align__(16) float d_g2[32 * 4096];                    // [b][j]  h @ Whh^T
__device__ __align__(16) float d_emb[32 * 1024];                   // [b][i]

// ---- f32x2 helpers ----
static __device__ __forceinline__ u64 dup2f(float a) {
    u64 r; asm("mov.b64 %0,{%1,%1};" : "=l"(r) : "f"(a)); return r;
}
static __device__ __forceinline__ void ffma2(u64& d, u64 a, u64 b) {
    asm("fma.rn.f32x2 %0,%1,%2,%0;" : "+l"(d) : "l"(a), "l"(b));
}
static __device__ __forceinline__ void unpack2(u64 v, float& a, float& b) {
    asm("mov.b64 {%0,%1},%2;" : "=f"(a), "=f"(b) : "l"(v));
}
static __device__ __forceinline__ float sigf(float x) { return 1.0f / (1.0f + expf(-x)); }

// ---- init: zero recurrent state ----
__global__ void k_init() {
    int i = blockIdx.x * blockDim.x + threadIdx.x;   // 512*256 = 131072 = 32*4096
    if (i < 32 * 1024) { d_c[i] = 0.0f; d_hWh[i] = 0.0f; }
    d_g2[i] = 0.0f;
}

// ---- K0: XE[r][h] = x_row[r] . Wx[h],  r=(t,b,p)  M=20480 N=1024 K=1024 ----
// tile 128x128, BK=16, 256 threads, micro 8x8 via f32x2 along n
__global__ __launch_bounds__(256) void k_xe(const float* __restrict__ x,
                                            const float* __restrict__ Wx) {
    __shared__ __align__(16) float As[16][132];
    __shared__ __align__(16) float Bs[16][132];
    __shared__ int Abase[128];
    const int tid = threadIdx.x;
    const int n0 = blockIdx.x * 128, m0 = blockIdx.y * 128;
    if (tid < 128) {
        int r = m0 + tid, t = r / 320, rem = r - t * 320, b = rem / 10, p = rem - b * 10;
        Abase[tid] = ((b * 64 + t) * 10 + p) * 1024;
    }
    __syncthreads();
    const int tm = tid >> 4, tn = tid & 15;
    u64 acc[8][4];
#pragma unroll
    for (int i = 0; i < 8; i++)
#pragma unroll
        for (int j = 0; j < 4; j++) acc[i][j] = 0ull;

    for (int k0 = 0; k0 < 1024; k0 += 16) {
#pragma unroll
        for (int l = 0; l < 2; l++) {
            int ii = tid + 256 * l, m = ii >> 2, c = ii & 3;
            float4 va = *(const float4*)&x[Abase[m] + k0 + c * 4];
            As[c * 4 + 0][m] = va.x; As[c * 4 + 1][m] = va.y;
            As[c * 4 + 2][m] = va.z; As[c * 4 + 3][m] = va.w;
            float4 vb = *(const float4*)&Wx[(size_t)(n0 + m) * 1024 + k0 + c * 4];
            Bs[c * 4 + 0][m] = vb.x; Bs[c * 4 + 1][m] = vb.y;
            Bs[c * 4 + 2][m] = vb.z; Bs[c * 4 + 3][m] = vb.w;
        }
        __syncthreads();
#pragma unroll
        for (int kk = 0; kk < 16; kk++) {
            float4 alo = *(const float4*)&As[kk][tm * 8];
            float4 ahi = *(const float4*)&As[kk][tm * 8 + 4];
            ulonglong2 bl = *(const ulonglong2*)&Bs[kk][tn * 8];
            ulonglong2 bh = *(const ulonglong2*)&Bs[kk][tn * 8 + 4];
            float a8[8] = {alo.x, alo.y, alo.z, alo.w, ahi.x, ahi.y, ahi.z, ahi.w};
#pragma unroll
            for (int r = 0; r < 8; r++) {
                u64 ad = dup2f(a8[r]);
                ffma2(acc[r][0], ad, bl.x); ffma2(acc[r][1], ad, bl.y);
                ffma2(acc[r][2], ad, bh.x); ffma2(acc[r][3], ad, bh.y);
            }
        }
        __syncthreads();
    }
#pragma unroll
    for (int r = 0; r < 8; r++) {
        float o[8];
        unpack2(acc[r][0], o[0], o[1]); unpack2(acc[r][1], o[2], o[3]);
        unpack2(acc[r][2], o[4], o[5]); unpack2(acc[r][3], o[6], o[7]);
        size_t row = (size_t)(m0 + tm * 8 + r);
        *(float4*)&d_XE[row * 1024 + n0 + tn * 8]     = make_float4(o[0], o[1], o[2], o[3]);
        *(float4*)&d_XE[row * 1024 + n0 + tn * 8 + 4] = make_float4(o[4], o[5], o[6], o[7]);
    }
}

// ---- attn(t): scores -> softmax over P=10 -> pooled emb. one block per b ----
__global__ __launch_bounds__(256) void k_attn(int t, const float* __restrict__ x,
                                              const float* __restrict__ b_att,
                                              const float* __restrict__ v) {
    const int b = blockIdx.x, tid = threadIdx.x;
    __shared__ float part[10][8];
    __shared__ float al[10];
    float ps[10];
#pragma unroll
    for (int p = 0; p < 10; p++) ps[p] = 0.0f;
    const float* xe = d_XE + (size_t)(t * 32 + b) * 10 * 1024;
    for (int h = tid; h < 1024; h += 256) {
        float base = d_hWh[b * 1024 + h] + b_att[h];
        float vh = v[h];
#pragma unroll
        for (int p = 0; p < 10; p++) {
            float e = tanhf(xe[p * 1024 + h] + base);
            ps[p] = fmaf(e, vh, ps[p]);
        }
    }
    int lane = tid & 31, w = tid >> 5;
#pragma unroll
    for (int p = 0; p < 10; p++) {
        float s = ps[p];
#pragma unroll
        for (int off = 16; off; off >>= 1) s += __shfl_xor_sync(0xffffffffu, s, off);
        if (lane == 0) part[p][w] = s;
    }
    __syncthreads();
    if (tid == 0) {
        float sc[10], mx = -1e30f;
#pragma unroll
        for (int p = 0; p < 10; p++) {
            float s = 0.0f;
#pragma unroll
            for (int q = 0; q < 8; q++) s += part[p][q];
            sc[p] = s; mx = fmaxf(mx, s);
        }
        float den = 0.0f;
#pragma unroll
        for (int p = 0; p < 10; p++) { sc[p] = expf(sc[p] - mx); den += sc[p]; }
        float inv = 1.0f / den;
#pragma unroll
        for (int p = 0; p < 10; p++) al[p] = sc[p] * inv;
    }
    __syncthreads();
    float a[10];
#pragma unroll
    for (int p = 0; p < 10; p++) a[p] = al[p];
    const float* xb = x + (size_t)(b * 64 + t) * 10 * 1024;
    for (int i = tid; i < 1024; i += 256) {
        float s = 0.0f;
#pragma unroll
        for (int p = 0; p < 10; p++) s = fmaf(a[p], xb[p * 1024 + i], s);
        d_emb[b * 1024 + i] = s;
    }
}

// ---- gates: g = emb@Wih^T (tile) + g2 + biases; fused LSTM cell update ----
// grid 128 blocks; block bj owns h-cols [bj*8, bj*8+8), j-tile = 4 gates x 8 h = 32 rows
__global__ __launch_bounds__(256) void k_gates(const float* __restrict__ Wih,
                                               const float* __restrict__ bih,
                                               const float* __restrict__ bhh) {
    __shared__ __align__(16) float Es[32][132];
    __shared__ __align__(16) float Ws[32][132];
    __shared__ float gs[32][33];
    const int tid = threadIdx.x, bj = blockIdx.x;
    const int tb = tid >> 4, tj = tid & 15;
    const int b0 = tb * 2, q0 = tj * 2;
    const int ldr = tid >> 3, seg = (tid & 7) * 16;
    const int jrow = (ldr >> 3) * 1024 + bj * 8 + (ldr & 7);   // Wih row for this loader
    float a00 = 0.f, a01 = 0.f, a10 = 0.f, a11 = 0.f;
    for (int k0 = 0; k0 < 1024; k0 += 128) {
#pragma unroll
        for (int d = 0; d < 4; d++) {
            *(float4*)&Es[ldr][seg + 4 * d] = *(const float4*)&d_emb[ldr * 1024 + k0 + seg + 4 * d];
            *(float4*)&Ws[ldr][seg + 4 * d] = *(const float4*)&Wih[(size_t)jrow * 1024 + k0 + seg + 4 * d];
        }
        __syncthreads();
#pragma unroll 4
        for (int kk = 0; kk < 128; kk += 4) {
            float4 e0 = *(const float4*)&Es[b0][kk];
            float4 e1 = *(const float4*)&Es[b0 + 1][kk];
            float4 w0 = *(const float4*)&Ws[q0][kk];
            float4 w1 = *(const float4*)&Ws[q0 + 1][kk];
            a00 = fmaf(e0.x, w0.x, a00); a00 = fmaf(e0.y, w0.y, a00);
            a00 = fmaf(e0.z, w0.z, a00); a00 = fmaf(e0.w, w0.w, a00);
            a01 = fmaf(e0.x, w1.x, a01); a01 = fmaf(e0.y, w1.y, a01);
            a01 = fmaf(e0.z, w1.z, a01); a01 = fmaf(e0.w, w1.w, a01);
            a10 = fmaf(e1.x, w0.x, a10); a10 = fmaf(e1.y, w0.y, a10);
            a10 = fmaf(e1.z, w0.z, a10); a10 = fmaf(e1.w, w0.w, a10);
            a11 = fmaf(e1.x, w1.x, a11); a11 = fmaf(e1.y, w1.y, a11);
            a11 = fmaf(e1.z, w1.z, a11); a11 = fmaf(e1.w, w1.w, a11);
        }
        __syncthreads();
    }
    gs[b0][q0] = a00; gs[b0][q0 + 1] = a01;
    gs[b0 + 1][q0] = a10; gs[b0 + 1][q0 + 1] = a11;
    __syncthreads();
    // cell update: 256 threads <-> 32 b x 8 h
    const int b = tid >> 3, hh = tid & 7;
    const int hcol = bj * 8 + hh;
    float gv[4];
#pragma unroll
    for (int g = 0; g < 4; g++) {
        int jr = g * 1024 + hcol;
        gv[g] = gs[b][g * 8 + hh] + d_g2[b * 4096 + jr] + bih[jr] + bhh[jr];
    }
    float cn = sigf(gv[1]) * d_c[b * 1024 + hcol] + sigf(gv[0]) * tanhf(gv[2]);
    float hn = sigf(gv[3]) * tanhf(cn);
    d_c[b * 1024 + hcol] = cn;
    d_h[b * 1024 + hcol] = hn;
}

// ---- rec: h @ [Whh;Wh]^T -> g2 (j<4096) and hWh (j>=4096). grid 160 ----
__global__ __launch_bounds__(256) void k_rec(const float* __restrict__ Whh,
                                             const float* __restrict__ Wh) {
    __shared__ __align__(16) float Es[32][132];
    __shared__ __align__(16) float Ws[32][132];
    const int tid = threadIdx.x, bj = blockIdx.x;
    const int tb = tid >> 4, tj = tid & 15;
    const int b0 = tb * 2, q0 = tj * 2;
    const int ldr = tid >> 3, seg = (tid & 7) * 16;
    const int jrow = bj * 32 + ldr;
    const float* src = (jrow < 4096) ? (Whh + (size_t)jrow * 1024)
                                     : (Wh + (size_t)(jrow - 4096) * 1024);
    float a00 = 0.f, a01 = 0.f, a10 = 0.f, a11 = 0.f;
    for (int k0 = 0; k0 < 1024; k0 += 128) {
#pragma unroll
        for (int d = 0; d < 4; d++) {
            *(float4*)&Es[ldr][seg + 4 * d] = *(const float4*)&d_h[ldr * 1024 + k0 + seg + 4 * d];
            *(float4*)&Ws[ldr][seg + 4 * d] = *(const float4*)&src[k0 + seg + 4 * d];
        }
        __syncthreads();
#pragma unroll 4
        for (int kk = 0; kk < 128; kk += 4) {
            float4 e0 = *(const float4*)&Es[b0][kk];
            float4 e1 = *(const float4*)&Es[b0 + 1][kk];
            float4 w0 = *(const float4*)&Ws[q0][kk];
            float4 w1 = *(const float4*)&Ws[q0 + 1][kk];
            a00 = fmaf(e0.x, w0.x, a00); a00 = fmaf(e0.y, w0.y, a00);
            a00 = fmaf(e0.z, w0.z, a00); a00 = fmaf(e0.w, w0.w, a00);
            a01 = fmaf(e0.x, w1.x, a01); a01 = fmaf(e0.y, w1.y, a01);
            a01 = fmaf(e0.z, w1.z, a01); a01 = fmaf(e0.w, w1.w, a01);
            a10 = fmaf(e1.x, w0.x, a10); a10 = fmaf(e1.y, w0.y, a10);
            a10 = fmaf(e1.z, w0.z, a10); a10 = fmaf(e1.w, w0.w, a10);
            a11 = fmaf(e1.x, w1.x, a11); a11 = fmaf(e1.y, w1.y, a11);
            a11 = fmaf(e1.z, w1.z, a11); a11 = fmaf(e1.w, w1.w, a11);
        }
        __syncthreads();
    }
    float res[2][2] = {{a00, a01}, {a10, a11}};
#pragma unroll
    for (int bi = 0; bi < 2; bi++)
#pragma unroll
        for (int qi = 0; qi < 2; qi++) {
            int j = bj * 32 + q0 + qi;
            int b = b0 + bi;
            if (j < 4096) d_g2[b * 4096 + j] = res[bi][qi];
            else          d_hWh[b * 1024 + (j - 4096)] = res[bi][qi];
        }
}

// ---- final FC: out[b][c] = h[b] . Wfc[c] + bfc[c]. 32 blocks x 8 warps ----
__global__ __launch_bounds__(256) void k_fc(const float* __restrict__ Wfc,
                                            const float* __restrict__ bfc,
                                            float* __restrict__ out) {
    const int b = blockIdx.x, w = threadIdx.x >> 5, lane = threadIdx.x & 31;
    const float* hr = d_h + b * 1024;
    const float* wr = Wfc + w * 1024;
    float s = 0.0f;
    for (int i = lane * 4; i < 1024; i += 128) {
        float4 hv = *(const float4*)&hr[i];
        float4 wv = *(const float4*)&wr[i];
        s = fmaf(hv.x, wv.x, s); s = fmaf(hv.y, wv.y, s);
        s = fmaf(hv.z, wv.z, s); s = fmaf(hv.w, wv.w, s);
    }
#pragma unroll
    for (int off = 16; off; off >>= 1) s += __shfl_xor_sync(0xffffffffu, s, off);
    if (lane == 0) out[b * 8 + w] = s + bfc[w];
}

extern "C" void kernel_launch(void* const* d_in, const int* in_sizes, int n_in,
                              void* d_out, int out_size) {
    const float* x     = (const float*)d_in[0];
    const float* Wx    = (const float*)d_in[1];
    const float* Wh    = (const float*)d_in[2];
    const float* b_att = (const float*)d_in[3];
    const float* v     = (const float*)d_in[4];
    const float* Wih   = (const float*)d_in[5];
    const float* Whh   = (const float*)d_in[6];
    const float* bih   = (const float*)d_in[7];
    const float* bhh   = (const float*)d_in[8];
    const float* Wfc   = (const float*)d_in[9];
    const float* bfc   = (const float*)d_in[10];
    float* out = (float*)d_out;

    k_init<<<512, 256>>>();
    k_xe<<<dim3(8, 160), 256>>>(x, Wx);
    for (int t = 0; t < 64; t++) {
        k_attn<<<32, 256>>>(t, x, b_att, v);
        k_gates<<<128, 256>>>(Wih, bih, bhh);
        if (t < 63) k_rec<<<160, 256>>>(Whh, Wh);
    }
    k_fc<<<32, 256>>>(Wfc, bfc, out);
}

// round 5
// speedup vs baseline: 1.9650x; 1.9650x over previous
#include <cuda_runtime.h>
#include <math.h>

typedef unsigned long long u64;

// ---- scratch (static device globals; no allocation) ----
__device__ __align__(16) float d_XE[(size_t)64 * 32 * 10 * 1024];  // 80MB  [t][b][p][h]
__device__ __align__(16) float d_h[32 * 1024];                     // [b][h]
__device__ __align__(16) float d_c[32 * 1024];                     // [b][h]
__device__ __align__(16) float d_hT[1024 * 32];                    // [h][b]
__device__ __align__(16) float d_embT[1024 * 32];                  // [i][b]
__device__ __align__(16) float d_g2T[4096 * 32];                   // [j][b]
__device__ __align__(16) float d_hWhT[1024 * 32];                  // [h][b]
__device__ __align__(16) float d_WrecB[640 * 8192];                // 20MB blocked [bj][k][8]
__device__ __align__(16) float d_WihB[512 * 8192];                 // 16MB blocked [bj][k][8]

// ---- f32x2 helpers ----
static __device__ __forceinline__ u64 dup2f(float a) {
    u64 r; asm("mov.b64 %0,{%1,%1};" : "=l"(r) : "f"(a)); return r;
}
static __device__ __forceinline__ void ffma2(u64& d, u64 a, u64 b) {
    asm("fma.rn.f32x2 %0,%1,%2,%0;" : "+l"(d) : "l"(a), "l"(b));
}
static __device__ __forceinline__ void unpack2(u64 v, float& a, float& b) {
    asm("mov.b64 {%0,%1},%2;" : "=f"(a), "=f"(b) : "l"(v));
}
static __device__ __forceinline__ float sigf(float x) { return 1.0f / (1.0f + expf(-x)); }

// ---- init: zero recurrent state ----
__global__ void k_init() {
    int i = blockIdx.x * blockDim.x + threadIdx.x;   // 512*256 = 131072
    d_g2T[i] = 0.0f;
    if (i < 32 * 1024) { d_c[i] = 0.0f; d_hWhT[i] = 0.0f; }
}

// ---- prep: blocked transpose of [Whh;Wh] -> WrecB[bj][k][s], j = bj*8+s ----
__global__ __launch_bounds__(256) void k_prep_rec(const float* __restrict__ Whh,
                                                  const float* __restrict__ Wh) {
    __shared__ __align__(16) float sm[32][36];
    const int tid = threadIdx.x;
    const int k0 = blockIdx.x * 32, jt = blockIdx.y;   // jt: 32-j group
    {
        int r = tid >> 3, c4 = (tid & 7) * 4;
        int j = jt * 32 + r;
        const float* src = (j < 4096) ? (Whh + (size_t)j * 1024) : (Wh + (size_t)(j - 4096) * 1024);
        *(float4*)&sm[r][c4] = *(const float4*)&src[k0 + c4];
    }
    __syncthreads();
    int kk = tid >> 3, s = tid & 7;
#pragma unroll
    for (int bji = 0; bji < 4; bji++) {
        d_WrecB[(size_t)(jt * 4 + bji) * 8192 + (k0 + kk) * 8 + s] = sm[bji * 8 + s][kk];
    }
}

// ---- prep: blocked transpose of Wih -> WihB[bj][k][s], s=(g,hh): j=g*1024+bj*2+hh ----
__global__ __launch_bounds__(256) void k_prep_ih(const float* __restrict__ Wih) {
    __shared__ __align__(16) float sm[32][36];
    const int tid = threadIdx.x;
    const int k0 = blockIdx.x * 32, grp = blockIdx.y;  // grp covers bj0=grp*4
    {
        int r = tid >> 3, c4 = (tid & 7) * 4;
        int g = r >> 3, bji = (r & 7) >> 1, hh = r & 1;
        int j = g * 1024 + (grp * 4 + bji) * 2 + hh;
        *(float4*)&sm[r][c4] = *(const float4*)&Wih[(size_t)j * 1024 + k0 + c4];
    }
    __syncthreads();
    int kk = tid >> 3, s = tid & 7;
    int g = s >> 1, hh = s & 1;
#pragma unroll
    for (int bji = 0; bji < 4; bji++) {
        d_WihB[(size_t)(grp * 4 + bji) * 8192 + (k0 + kk) * 8 + s] = sm[g * 8 + bji * 2 + hh][kk];
    }
}

// ---- K0: XE[r][h] = x_row[r] . Wx[h],  r=(t,b,p)  M=20480 N=1024 K=1024 ----
__global__ __launch_bounds__(256) void k_xe(const float* __restrict__ x,
                                            const float* __restrict__ Wx) {
    __shared__ __align__(16) float As[16][132];
    __shared__ __align__(16) float Bs[16][132];
    __shared__ int Abase[128];
    const int tid = threadIdx.x;
    const int n0 = blockIdx.x * 128, m0 = blockIdx.y * 128;
    if (tid < 128) {
        int r = m0 + tid, t = r / 320, rem = r - t * 320, b = rem / 10, p = rem - b * 10;
        Abase[tid] = ((b * 64 + t) * 10 + p) * 1024;
    }
    __syncthreads();
    const int tm = tid >> 4, tn = tid & 15;
    u64 acc[8][4];
#pragma unroll
    for (int i = 0; i < 8; i++)
#pragma unroll
        for (int j = 0; j < 4; j++) acc[i][j] = 0ull;

    for (int k0 = 0; k0 < 1024; k0 += 16) {
#pragma unroll
        for (int l = 0; l < 2; l++) {
            int ii = tid + 256 * l, m = ii >> 2, c = ii & 3;
            float4 va = *(const float4*)&x[Abase[m] + k0 + c * 4];
            As[c * 4 + 0][m] = va.x; As[c * 4 + 1][m] = va.y;
            As[c * 4 + 2][m] = va.z; As[c * 4 + 3][m] = va.w;
            float4 vb = *(const float4*)&Wx[(size_t)(n0 + m) * 1024 + k0 + c * 4];
            Bs[c * 4 + 0][m] = vb.x; Bs[c * 4 + 1][m] = vb.y;
            Bs[c * 4 + 2][m] = vb.z; Bs[c * 4 + 3][m] = vb.w;
        }
        __syncthreads();
#pragma unroll
        for (int kk = 0; kk < 16; kk++) {
            float4 alo = *(const float4*)&As[kk][tm * 8];
            float4 ahi = *(const float4*)&As[kk][tm * 8 + 4];
            ulonglong2 bl = *(const ulonglong2*)&Bs[kk][tn * 8];
            ulonglong2 bh = *(const ulonglong2*)&Bs[kk][tn * 8 + 4];
            float a8[8] = {alo.x, alo.y, alo.z, alo.w, ahi.x, ahi.y, ahi.z, ahi.w};
#pragma unroll
            for (int r = 0; r < 8; r++) {
                u64 ad = dup2f(a8[r]);
                ffma2(acc[r][0], ad, bl.x); ffma2(acc[r][1], ad, bl.y);
                ffma2(acc[r][2], ad, bh.x); ffma2(acc[r][3], ad, bh.y);
            }
        }
        __syncthreads();
    }
#pragma unroll
    for (int r = 0; r < 8; r++) {
        float o[8];
        unpack2(acc[r][0], o[0], o[1]); unpack2(acc[r][1], o[2], o[3]);
        unpack2(acc[r][2], o[4], o[5]); unpack2(acc[r][3], o[6], o[7]);
        size_t row = (size_t)(m0 + tm * 8 + r);
        *(float4*)&d_XE[row * 1024 + n0 + tn * 8]     = make_float4(o[0], o[1], o[2], o[3]);
        *(float4*)&d_XE[row * 1024 + n0 + tn * 8 + 4] = make_float4(o[4], o[5], o[6], o[7]);
    }
}

// ---- attn(t): 32 blocks x 1024 thr. scores -> softmax(P=10) -> pooled embT ----
__global__ __launch_bounds__(1024) void k_attn(int t, const float* __restrict__ x,
                                               const float* __restrict__ b_att,
                                               const float* __restrict__ v) {
    const int b = blockIdx.x, tid = threadIdx.x;
    __shared__ float sm[10][33];
    __shared__ float al[10];
    const int h = tid;
    const float base = d_hWhT[h * 32 + b] + b_att[h];
    const float vh = v[h];
    const float* xe = d_XE + (size_t)(t * 32 + b) * 10 * 1024;
    float ps[10];
#pragma unroll
    for (int p = 0; p < 10; p++) {
        float e = tanhf(xe[p * 1024 + h] + base);
        ps[p] = e * vh;
    }
    const int lane = tid & 31, w = tid >> 5;
#pragma unroll
    for (int p = 0; p < 10; p++) {
        float s = ps[p];
#pragma unroll
        for (int off = 16; off; off >>= 1) s += __shfl_xor_sync(0xffffffffu, s, off);
        if (lane == 0) sm[p][w] = s;
    }
    __syncthreads();
    if (tid < 320) {
        int p = tid >> 5;
        float s = sm[p][lane];
#pragma unroll
        for (int off = 16; off; off >>= 1) s += __shfl_xor_sync(0xffffffffu, s, off);
        if (lane == 0) sm[p][32] = s;
    }
    __syncthreads();
    if (tid == 0) {
        float sc[10], mx = -1e30f;
#pragma unroll
        for (int p = 0; p < 10; p++) { sc[p] = sm[p][32]; mx = fmaxf(mx, sc[p]); }
        float den = 0.0f;
#pragma unroll
        for (int p = 0; p < 10; p++) { sc[p] = expf(sc[p] - mx); den += sc[p]; }
        float inv = 1.0f / den;
#pragma unroll
        for (int p = 0; p < 10; p++) al[p] = sc[p] * inv;
    }
    __syncthreads();
    float a[10];
#pragma unroll
    for (int p = 0; p < 10; p++) a[p] = al[p];
    const float* xb = x + (size_t)(b * 64 + t) * 10 * 1024;
    float s = 0.0f;
#pragma unroll
    for (int p = 0; p < 10; p++) s = fmaf(a[p], xb[p * 1024 + tid], s);
    d_embT[tid * 32 + b] = s;
}

// ---- gates: 512 blocks. block bj -> h cols {bj*2, bj*2+1} x 4 gates. fused cell ----
__global__ __launch_bounds__(256) void k_gates(const float* __restrict__ bih,
                                               const float* __restrict__ bhh) {
    __shared__ __align__(16) float ws[1024][8];       // 32KB weight slice
    __shared__ float ps[8][8][32];                    // 8KB partials [warp][slot][b]
    __shared__ float gvs[8][32];
    const int tid = threadIdx.x, bj = blockIdx.x;
    const float4* wb = (const float4*)(d_WihB + (size_t)bj * 8192);
#pragma unroll
    for (int i = 0; i < 8; i++) ((float4*)ws)[tid + i * 256] = wb[tid + i * 256];
    __syncthreads();
    const int w = tid >> 5, lane = tid & 31;
    u64 acc[4] = {0ull, 0ull, 0ull, 0ull};
    const float* eb = d_embT + w * 128 * 32 + lane;
#pragma unroll 4
    for (int k = 0; k < 128; k++) {
        u64 ed = dup2f(eb[k * 32]);
        int kk = w * 128 + k;
        ulonglong2 w01 = *(const ulonglong2*)&ws[kk][0];
        ulonglong2 w23 = *(const ulonglong2*)&ws[kk][4];
        ffma2(acc[0], ed, w01.x); ffma2(acc[1], ed, w01.y);
        ffma2(acc[2], ed, w23.x); ffma2(acc[3], ed, w23.y);
    }
#pragma unroll
    for (int q = 0; q < 4; q++) {
        float a, b2; unpack2(acc[q], a, b2);
        ps[w][2 * q][lane] = a; ps[w][2 * q + 1][lane] = b2;
    }
    __syncthreads();
    {
        const int s = tid >> 5, b = tid & 31;
        float r = 0.0f;
#pragma unroll
        for (int q = 0; q < 8; q++) r += ps[q][s][b];
        int g = s >> 1, hh = s & 1;
        int j = g * 1024 + bj * 2 + hh;
        r += d_g2T[j * 32 + b] + bih[j] + bhh[j];
        gvs[s][b] = r;
    }
    __syncthreads();
    if (tid < 64) {
        int b = tid >> 1, hh = tid & 1;
        int h = bj * 2 + hh;
        float iv = gvs[0 + hh][b], fv = gvs[2 + hh][b];
        float gv = gvs[4 + hh][b], ov = gvs[6 + hh][b];
        float c = d_c[b * 1024 + h];
        float cn = sigf(fv) * c + sigf(iv) * tanhf(gv);
        float hn = sigf(ov) * tanhf(cn);
        d_c[b * 1024 + h] = cn;
        d_h[b * 1024 + h] = hn;
        d_hT[h * 32 + b] = hn;
    }
}

// ---- rec: 640 blocks. h @ [Whh;Wh]^T -> g2T (j<4096) / hWhT ----
__global__ __launch_bounds__(256) void k_rec() {
    __shared__ __align__(16) float ws[1024][8];
    __shared__ float ps[8][8][32];
    const int tid = threadIdx.x, bj = blockIdx.x;
    const float4* wb = (const float4*)(d_WrecB + (size_t)bj * 8192);
#pragma unroll
    for (int i = 0; i < 8; i++) ((float4*)ws)[tid + i * 256] = wb[tid + i * 256];
    __syncthreads();
    const int w = tid >> 5, lane = tid & 31;
    u64 acc[4] = {0ull, 0ull, 0ull, 0ull};
    const float* eb = d_hT + w * 128 * 32 + lane;
#pragma unroll 4
    for (int k = 0; k < 128; k++) {
        u64 ed = dup2f(eb[k * 32]);
        int kk = w * 128 + k;
        ulonglong2 w01 = *(const ulonglong2*)&ws[kk][0];
        ulonglong2 w23 = *(const ulonglong2*)&ws[kk][4];
        ffma2(acc[0], ed, w01.x); ffma2(acc[1], ed, w01.y);
        ffma2(acc[2], ed, w23.x); ffma2(acc[3], ed, w23.y);
    }
#pragma unroll
    for (int q = 0; q < 4; q++) {
        float a, b2; unpack2(acc[q], a, b2);
        ps[w][2 * q][lane] = a; ps[w][2 * q + 1][lane] = b2;
    }
    __syncthreads();
    const int s = tid >> 5, b = tid & 31;
    float r = 0.0f;
#pragma unroll
    for (int q = 0; q < 8; q++) r += ps[q][s][b];
    int j = bj * 8 + s;
    if (j < 4096) d_g2T[j * 32 + b] = r;
    else          d_hWhT[(j - 4096) * 32 + b] = r;
}

// ---- final FC ----
__global__ __launch_bounds__(256) void k_fc(const float* __restrict__ Wfc,
                                            const float* __restrict__ bfc,
                                            float* __restrict__ out) {
    const int b = blockIdx.x, w = threadIdx.x >> 5, lane = threadIdx.x & 31;
    const float* hr = d_h + b * 1024;
    const float* wr = Wfc + w * 1024;
    float s = 0.0f;
    for (int i = lane * 4; i < 1024; i += 128) {
        float4 hv = *(const float4*)&hr[i];
        float4 wv = *(const float4*)&wr[i];
        s = fmaf(hv.x, wv.x, s); s = fmaf(hv.y, wv.y, s);
        s = fmaf(hv.z, wv.z, s); s = fmaf(hv.w, wv.w, s);
    }
#pragma unroll
    for (int off = 16; off; off >>= 1) s += __shfl_xor_sync(0xffffffffu, s, off);
    if (lane == 0) out[b * 8 + w] = s + bfc[w];
}

extern "C" void kernel_launch(void* const* d_in, const int* in_sizes, int n_in,
                              void* d_out, int out_size) {
    const float* x     = (const float*)d_in[0];
    const float* Wx    = (const float*)d_in[1];
    const float* Wh    = (const float*)d_in[2];
    const float* b_att = (const float*)d_in[3];
    const float* v     = (const float*)d_in[4];
    const float* Wih   = (const float*)d_in[5];
    const float* Whh   = (const float*)d_in[6];
    const float* bih   = (const float*)d_in[7];
    const float* bhh   = (const float*)d_in[8];
    const float* Wfc   = (const float*)d_in[9];
    const float* bfc   = (const float*)d_in[10];
    float* out = (float*)d_out;

    k_init<<<512, 256>>>();
    k_prep_rec<<<dim3(32, 160), 256>>>(Whh, Wh);
    k_prep_ih<<<dim3(32, 128), 256>>>(Wih);
    k_xe<<<dim3(8, 160), 256>>>(x, Wx);
    for (int t = 0; t < 64; t++) {
        k_attn<<<32, 1024>>>(t, x, b_att, v);
        k_gates<<<512, 256>>>(bih, bhh);
        if (t < 63) k_rec<<<640, 256>>>();
    }
    k_fc<<<32, 256>>>(Wfc, bfc, out);
}